// round 14
// baseline (speedup 1.0000x reference)
#include <cuda_runtime.h>
#include <math.h>

// Problem constants
constexpr int Hc   = 20;          // H
constexpr int H2c  = 40;          // 2H
constexpr int Tc   = 512;
constexpr int Dc   = 128;
constexpr int Nc   = 1024;
// Tail timesteps kept. |alpha| <= |u||z| = sqrt(2H)/H < 0.3163 rigorously,
// so truncation error <= alpha^{KT-1} ~ 3e-8 at KT=16 — far below fp32 noise.
// bias = beta*a0*alpha^511 < 1e-255 -> exact fp32 zero: dropped entirely.
constexpr int KT   = 16;
constexpr int ROWS_PER_BLK = 4;               // samples per block (grid = 256)
constexpr int F4_PER_ROW   = KT * Dc / 4;     // 512 float4 per sample tail (pow2)
constexpr int F4_PER_BLK   = ROWS_PER_BLK * F4_PER_ROW;   // 2048 (32 KB)
constexpr float PIf = 3.14159265358979323846f;

// ---------------------------------------------------------------------------
// Single fused kernel — R13 champion + Cw smem prefetch (cp.async group 0).
//   recurrence(h) = (u . h) * z  (rank-1), so
//   y_n = q.x[n,T-1] + sum_{k<=KT-2} beta*alpha^{KT-2-k} (p.x[n,T-KT+k])
// ---------------------------------------------------------------------------
__global__ __launch_bounds__(256)
void urnn_fused(const float* __restrict__ x,     // (1024,512,128)
                const float* __restrict__ Cw,    // (40,128)
                const float* __restrict__ Bw,    // (1,40)
                const float* __restrict__ refl,  // (2,40)
                const float* __restrict__ theta, // (3,20)
                const float* __restrict__ mu0,   // unused (bias == 0)
                float* __restrict__ out)         // (1024,)
{
    __shared__ float4 sX[F4_PER_BLK];            // 32 KB
    __shared__ float  sCw[H2c * Dc];             // 20 KB
    __shared__ float tw_c[Hc], tw_s[Hc];
    __shared__ float e0c[Hc], e0s[Hc];
    __shared__ float z0r[Hc], z0i[Hc];
    __shared__ float e2c[Hc], e2s[Hc];
    __shared__ float r1[H2c], r2[H2c], sBw[H2c];
    __shared__ float su[H2c];
    __shared__ float so_r[Hc], so_i[Hc];
    __shared__ float sp[Dc], sq[Dc], scoef[KT];
    __shared__ float vss1s, vss2s;
    __shared__ float wsum[8];

    const int tid  = threadIdx.x;
    const int lane = tid & 31;
    const int warp = tid >> 5;
    const unsigned FULL = 0xffffffffu;

    // ---- cp.async: Cw (group 0), then x tail (group 1), both at cycle ~0 ----
    {
        const float4* cwsrc = reinterpret_cast<const float4*>(Cw);
        #pragma unroll
        for (int r = 0; r < 5; r++) {                     // 1280 float4 = 20 KB
            const int idx = tid + r * 256;
            unsigned sa = (unsigned)__cvta_generic_to_shared(
                reinterpret_cast<float4*>(sCw) + idx);
            asm volatile("cp.async.cg.shared.global [%0], [%1], 16;\n"
                         :: "r"(sa), "l"(cwsrc + idx));
        }
        asm volatile("cp.async.commit_group;\n");

        const int n0 = blockIdx.x * ROWS_PER_BLK;
        #pragma unroll
        for (int r = 0; r < F4_PER_BLK / 256; r++) {      // 8 per thread
            const int idx = tid + r * 256;                // 0..2047
            const int s   = idx >> 9;                     // sample within block
            const int w   = idx & (F4_PER_ROW - 1);       // float4 within sample
            const float4* src = reinterpret_cast<const float4*>(
                x + (size_t)(n0 + s) * (Tc * Dc) + (size_t)(Tc - KT) * Dc) + w;
            unsigned sa = (unsigned)__cvta_generic_to_shared(&sX[idx]);
            asm volatile("cp.async.cg.shared.global [%0], [%1], 16;\n"
                         :: "r"(sa), "l"(src));
        }
        asm volatile("cp.async.commit_group;\n");
    }

    // ---- Pre-stage (parallel): fast trig tables, operand staging, vss ----
    if (tid < Hc) {
        float s, c;
        __sincosf(2.0f * PIf * (float)tid / (float)Hc, &s, &c);
        tw_c[tid] = c; tw_s[tid] = s;
        __sincosf(theta[tid], &s, &c);          e0c[tid] = c; e0s[tid] = s;
        __sincosf(theta[Hc + tid], &s, &c);     z0r[tid] = c - s; z0i[tid] = c + s;
        __sincosf(theta[2 * Hc + tid], &s, &c); e2c[tid] = c; e2s[tid] = s;
    }
    if (tid >= 32 && tid < 32 + H2c) {
        const int j = tid - 32;
        r1[j] = refl[j]; r2[j] = refl[H2c + j]; sBw[j] = Bw[j];
    }
    if (warp == 3) {                                   // vss1 = |v1|^2 (butterfly)
        float v = refl[lane] * refl[lane];
        if (lane + 32 < H2c) { float r = refl[lane + 32]; v += r * r; }
        #pragma unroll
        for (int off = 16; off; off >>= 1) v += __shfl_xor_sync(FULL, v, off);
        if (lane == 0) vss1s = v;
    }
    if (warp == 4) {                                   // vss2 = |v2|^2 (butterfly)
        float v = refl[H2c + lane] * refl[H2c + lane];
        if (lane + 32 < H2c) { float r = refl[H2c + lane + 32]; v += r * r; }
        #pragma unroll
        for (int off = 16; off; off >>= 1) v += __shfl_xor_sync(FULL, v, off);
        if (lane == 0) vss2s = v;
    }
    __syncthreads();                                   // sync0

    // ---- Stage A (warps 0-1): u_j = Im[(w_j/sqrtH)(1 - s1 V_m conj(v1_0))] ----
    if (tid < H2c) {
        const int j = tid;
        const int m = (j < Hc) ? j : j - Hc;
        float2 w;
        if (j < Hc) w = make_float2(e0c[m], e0s[m]);
        else        w = make_float2(-e0s[m], e0c[m]);   // i * e^{i th}
        const float sc1 = 2.0f / vss1s;
        float Vx = 0.f, Vy = 0.f;
        #pragma unroll 4
        for (int k = 0; k < Hc; k++) {
            const int mm = (m * k) % Hc;
            const float ck = tw_c[mm], sk = -tw_s[mm];  // exp(-2*pi*i*mm/H)
            const float vr = r1[k], vi = r1[Hc + k];
            Vx += vr * ck - vi * sk;
            Vy += vr * sk + vi * ck;
        }
        const float v0x = r1[0], v0y = -r1[Hc];         // conj(v1_0)
        const float gx = 1.0f - sc1 * (Vx * v0x - Vy * v0y);
        const float gy =        -sc1 * (Vx * v0y + Vy * v0x);
        su[j] = (w.x * gy + w.y * gx) * (1.0f / sqrtf((float)Hc));
    }
    // ---- Stage B1 (warp 2, concurrent): o = IFFT(z0)/sqrtH ----
    if (tid >= 64 && tid < 64 + Hc) {
        const int k = tid - 64;
        float ar = 0.f, ai = 0.f;
        #pragma unroll 4
        for (int m = 0; m < Hc; m++) {
            const int mm = (m * k) % Hc;
            const float ck = tw_c[mm], sk = tw_s[mm];   // exp(+2*pi*i*mm/H)
            ar += z0r[m] * ck - z0i[m] * sk;
            ai += z0r[m] * sk + z0i[m] * ck;
        }
        const float scale = 1.0f / ((float)Hc * sqrtf((float)Hc));
        so_r[k] = ar * scale; so_i[k] = ai * scale;
    }
    // Cw prefetch (group 0) must be complete and visible after this barrier.
    asm volatile("cp.async.wait_group 1;\n" ::: "memory");
    __syncthreads();                                   // sync1

    // ---- Warp 0: B2 + B3 + C, barrier-free (two short butterflies) ----
    if (warp == 0) {
        const int k = lane;
        const bool act = (k < Hc);
        const float vr = act ? r2[k] : 0.f;
        const float vi = act ? r2[Hc + k] : 0.f;
        const float orr = act ? so_r[k] : 0.f;
        const float oii = act ? so_i[k] : 0.f;
        // B2: t2 = (2/vss2) * (v2^T o)
        float tx = vr * orr - vi * oii;
        float ty = vr * oii + vi * orr;
        #pragma unroll
        for (int off = 16; off; off >>= 1) {
            tx += __shfl_xor_sync(FULL, tx, off);
            ty += __shfl_xor_sync(FULL, ty, off);
        }
        const float s2 = 2.0f / vss2s;
        const float t2x = tx * s2, t2y = ty * s2;
        // B3 (registers): z = D3 * (o - t2*conj(v2))
        float zr = 0.f, zi = 0.f;
        if (act) {
            const float ox = orr - (t2x * vr + t2y * vi);
            const float oy = oii - (t2y * vr - t2x * vi);
            const float c = e2c[k], s = e2s[k];
            zr = ox * c - oy * s;
            zi = ox * s + oy * c;
        }
        // C: alpha = u.z, beta = z.Bw (butterflies)
        float ap = act ? su[k] * zr + su[Hc + k] * zi : 0.f;
        float bp = act ? zr * sBw[k] + zi * sBw[Hc + k] : 0.f;
        #pragma unroll
        for (int off = 16; off; off >>= 1) {
            ap += __shfl_xor_sync(FULL, ap, off);
            bp += __shfl_xor_sync(FULL, bp, off);
        }
        // coef ladder, per-lane (<=14 serial multiplies, parallel across lanes)
        if (lane < KT) {
            float c;
            if (lane == KT - 1) c = 1.0f;               // slot for q
            else {
                c = bp;
                for (int e = 0; e < KT - 2 - lane; e++) c *= ap;
            }
            scoef[lane] = c;
        }
    }
    // ---- Warps 4-7 (concurrent): p = Cw^T u, q = Cw^T b from smem ----
    if (tid >= 128) {
        const int d = tid - 128;
        float p = 0.f, q = 0.f;
        #pragma unroll 8
        for (int j = 0; j < H2c; j++) {
            const float cw = sCw[j * Dc + d];
            p += su[j] * cw;
            q += sBw[j] * cw;
        }
        sp[d] = p; sq[d] = q;
    }

    // ---- Wait for x tail, then dot ----
    asm volatile("cp.async.wait_group 0;\n" ::: "memory");
    __syncthreads();                                   // sync2

    // 64 threads per sample; thread covers float4 indices st + 64r (r=0..7).
    // k = (st + 64r) >> 5 = 2r + warpInSample -> warp-uniform, k in 0..15.
    const int s   = tid >> 6;                          // sample within block
    const int st  = tid & 63;                          // thread within sample
    const int wis = (tid >> 5) & 1;                    // warp within sample

    const float4 pv = reinterpret_cast<const float4*>(sp)[lane];
    const float4 qv = reinterpret_cast<const float4*>(sq)[lane];

    float acc = 0.f;
    #pragma unroll
    for (int r = 0; r < KT / 2; r++) {
        const int k = 2 * r + wis;                     // timestep, warp-uniform
        const float4 xv = sX[s * F4_PER_ROW + st + r * 64];
        const float4 wv = (k == KT - 1) ? qv : pv;
        const float d = xv.x * wv.x + xv.y * wv.y + xv.z * wv.z + xv.w * wv.w;
        acc += scoef[k] * d;
    }

    #pragma unroll
    for (int off = 16; off; off >>= 1) acc += __shfl_down_sync(FULL, acc, off);
    if (lane == 0) wsum[warp] = acc;
    __syncthreads();                                   // sync3
    if (tid < ROWS_PER_BLK)
        out[blockIdx.x * ROWS_PER_BLK + tid] = wsum[2 * tid] + wsum[2 * tid + 1];
}

extern "C" void kernel_launch(void* const* d_in, const int* in_sizes, int n_in,
                              void* d_out, int out_size)
{
    const float* inputs = (const float*)d_in[0];   // (1024, 512, 128)
    const float* C_w    = (const float*)d_in[1];   // (40, 128)
    const float* B_w    = (const float*)d_in[2];   // (1, 40)
    const float* refl   = (const float*)d_in[3];   // (2, 40)
    const float* theta  = (const float*)d_in[4];   // (3, 20)
    const float* mu0    = (const float*)d_in[5];   // (20,)
    float* out = (float*)d_out;                    // (1024,)

    urnn_fused<<<Nc / ROWS_PER_BLK, 256>>>(inputs, C_w, B_w, refl, theta, mu0, out);
}

// round 15
// speedup vs baseline: 1.0037x; 1.0037x over previous
#include <cuda_runtime.h>
#include <math.h>

// Problem constants
constexpr int Hc   = 20;          // H
constexpr int H2c  = 40;          // 2H
constexpr int Tc   = 512;
constexpr int Dc   = 128;
constexpr int Nc   = 1024;
// Tail timesteps kept. |alpha| <= |u||z| = sqrt(2H)/H < 0.3163 rigorously,
// so truncation error <= alpha^{KT-1} ~ 3e-8 at KT=16 — far below fp32 noise.
// bias = beta*a0*alpha^511 < 1e-255 -> exact fp32 zero: dropped entirely.
constexpr int KT   = 16;
constexpr int ROWS_PER_BLK = 4;               // samples per block (grid = 256)
constexpr int F4_PER_ROW   = KT * Dc / 4;     // 512 float4 per sample tail
constexpr float PIf = 3.14159265358979323846f;

// ---------------------------------------------------------------------------
// Single fused kernel — R14 structure, x tail held in REGISTERS (no smem
// round trip; loads issued first, consumed last, scoreboard hides setup).
//   recurrence(h) = (u . h) * z  (rank-1), so
//   y_n = q.x[n,T-1] + sum_{k<=KT-2} beta*alpha^{KT-2-k} (p.x[n,T-KT+k])
// ---------------------------------------------------------------------------
__global__ __launch_bounds__(256)
void urnn_fused(const float* __restrict__ x,     // (1024,512,128)
                const float* __restrict__ Cw,    // (40,128)
                const float* __restrict__ Bw,    // (1,40)
                const float* __restrict__ refl,  // (2,40)
                const float* __restrict__ theta, // (3,20)
                const float* __restrict__ mu0,   // unused (bias == 0)
                float* __restrict__ out)         // (1024,)
{
    __shared__ float  sCw[H2c * Dc];             // 20 KB
    __shared__ float tw_c[Hc], tw_s[Hc];
    __shared__ float e0c[Hc], e0s[Hc];
    __shared__ float z0r[Hc], z0i[Hc];
    __shared__ float e2c[Hc], e2s[Hc];
    __shared__ float r1[H2c], r2[H2c], sBw[H2c];
    __shared__ float su[H2c];
    __shared__ float so_r[Hc], so_i[Hc];
    __shared__ float sp[Dc], sq[Dc], scoef[KT];
    __shared__ float vss1s, vss2s;
    __shared__ float wsum[8];

    const int tid  = threadIdx.x;
    const int lane = tid & 31;
    const int warp = tid >> 5;
    const unsigned FULL = 0xffffffffu;

    // ---- x tail straight into registers, issued FIRST ----
    // 64 threads per sample; thread covers float4 indices st + 64r (r=0..7).
    const int s   = tid >> 6;                  // sample within block (0..3)
    const int st  = tid & 63;                  // thread within sample
    const int wis = (tid >> 5) & 1;            // warp within sample
    const float4* xp = reinterpret_cast<const float4*>(
        x + (size_t)(blockIdx.x * ROWS_PER_BLK + s) * (Tc * Dc)
          + (size_t)(Tc - KT) * Dc);
    float4 xv[8];
    #pragma unroll
    for (int r = 0; r < 8; r++) xv[r] = __ldg(xp + st + r * 64);

    // ---- cp.async: Cw prefetch (group 0) ----
    {
        const float4* cwsrc = reinterpret_cast<const float4*>(Cw);
        #pragma unroll
        for (int r = 0; r < 5; r++) {                     // 1280 float4 = 20 KB
            const int idx = tid + r * 256;
            unsigned sa = (unsigned)__cvta_generic_to_shared(
                reinterpret_cast<float4*>(sCw) + idx);
            asm volatile("cp.async.cg.shared.global [%0], [%1], 16;\n"
                         :: "r"(sa), "l"(cwsrc + idx));
        }
        asm volatile("cp.async.commit_group;\n");
    }

    // ---- Pre-stage (parallel): fast trig tables, operand staging, vss ----
    if (tid < Hc) {
        float sv, cv;
        __sincosf(2.0f * PIf * (float)tid / (float)Hc, &sv, &cv);
        tw_c[tid] = cv; tw_s[tid] = sv;
        __sincosf(theta[tid], &sv, &cv);          e0c[tid] = cv; e0s[tid] = sv;
        __sincosf(theta[Hc + tid], &sv, &cv);     z0r[tid] = cv - sv; z0i[tid] = cv + sv;
        __sincosf(theta[2 * Hc + tid], &sv, &cv); e2c[tid] = cv; e2s[tid] = sv;
    }
    if (tid >= 32 && tid < 32 + H2c) {
        const int j = tid - 32;
        r1[j] = refl[j]; r2[j] = refl[H2c + j]; sBw[j] = Bw[j];
    }
    if (warp == 3) {                                   // vss1 = |v1|^2 (butterfly)
        float v = refl[lane] * refl[lane];
        if (lane + 32 < H2c) { float r = refl[lane + 32]; v += r * r; }
        #pragma unroll
        for (int off = 16; off; off >>= 1) v += __shfl_xor_sync(FULL, v, off);
        if (lane == 0) vss1s = v;
    }
    if (warp == 4) {                                   // vss2 = |v2|^2 (butterfly)
        float v = refl[H2c + lane] * refl[H2c + lane];
        if (lane + 32 < H2c) { float r = refl[H2c + lane + 32]; v += r * r; }
        #pragma unroll
        for (int off = 16; off; off >>= 1) v += __shfl_xor_sync(FULL, v, off);
        if (lane == 0) vss2s = v;
    }
    __syncthreads();                                   // sync0

    // ---- Stage A (warps 0-1): u_j = Im[(w_j/sqrtH)(1 - s1 V_m conj(v1_0))] ----
    if (tid < H2c) {
        const int j = tid;
        const int m = (j < Hc) ? j : j - Hc;
        float2 w;
        if (j < Hc) w = make_float2(e0c[m], e0s[m]);
        else        w = make_float2(-e0s[m], e0c[m]);   // i * e^{i th}
        const float sc1 = 2.0f / vss1s;
        float Vx = 0.f, Vy = 0.f;
        #pragma unroll 4
        for (int k = 0; k < Hc; k++) {
            const int mm = (m * k) % Hc;
            const float ck = tw_c[mm], sk = -tw_s[mm];  // exp(-2*pi*i*mm/H)
            const float vr = r1[k], vi = r1[Hc + k];
            Vx += vr * ck - vi * sk;
            Vy += vr * sk + vi * ck;
        }
        const float v0x = r1[0], v0y = -r1[Hc];         // conj(v1_0)
        const float gx = 1.0f - sc1 * (Vx * v0x - Vy * v0y);
        const float gy =        -sc1 * (Vx * v0y + Vy * v0x);
        su[j] = (w.x * gy + w.y * gx) * (1.0f / sqrtf((float)Hc));
    }
    // ---- Stage B1 (warp 2, concurrent): o = IFFT(z0)/sqrtH ----
    if (tid >= 64 && tid < 64 + Hc) {
        const int k = tid - 64;
        float ar = 0.f, ai = 0.f;
        #pragma unroll 4
        for (int m = 0; m < Hc; m++) {
            const int mm = (m * k) % Hc;
            const float ck = tw_c[mm], sk = tw_s[mm];   // exp(+2*pi*i*mm/H)
            ar += z0r[m] * ck - z0i[m] * sk;
            ai += z0r[m] * sk + z0i[m] * ck;
        }
        const float scale = 1.0f / ((float)Hc * sqrtf((float)Hc));
        so_r[k] = ar * scale; so_i[k] = ai * scale;
    }
    // Cw prefetch (group 0) must be complete and visible after this barrier.
    asm volatile("cp.async.wait_group 0;\n" ::: "memory");
    __syncthreads();                                   // sync1

    // ---- Warp 0: B2 + B3 + C, barrier-free (two short butterflies) ----
    if (warp == 0) {
        const int k = lane;
        const bool act = (k < Hc);
        const float vr = act ? r2[k] : 0.f;
        const float vi = act ? r2[Hc + k] : 0.f;
        const float orr = act ? so_r[k] : 0.f;
        const float oii = act ? so_i[k] : 0.f;
        // B2: t2 = (2/vss2) * (v2^T o)
        float tx = vr * orr - vi * oii;
        float ty = vr * oii + vi * orr;
        #pragma unroll
        for (int off = 16; off; off >>= 1) {
            tx += __shfl_xor_sync(FULL, tx, off);
            ty += __shfl_xor_sync(FULL, ty, off);
        }
        const float s2 = 2.0f / vss2s;
        const float t2x = tx * s2, t2y = ty * s2;
        // B3 (registers): z = D3 * (o - t2*conj(v2))
        float zr = 0.f, zi = 0.f;
        if (act) {
            const float ox = orr - (t2x * vr + t2y * vi);
            const float oy = oii - (t2y * vr - t2x * vi);
            const float c = e2c[k], sv = e2s[k];
            zr = ox * c - oy * sv;
            zi = ox * sv + oy * c;
        }
        // C: alpha = u.z, beta = z.Bw (butterflies)
        float ap = act ? su[k] * zr + su[Hc + k] * zi : 0.f;
        float bp = act ? zr * sBw[k] + zi * sBw[Hc + k] : 0.f;
        #pragma unroll
        for (int off = 16; off; off >>= 1) {
            ap += __shfl_xor_sync(FULL, ap, off);
            bp += __shfl_xor_sync(FULL, bp, off);
        }
        // coef ladder, per-lane (<=14 serial multiplies, parallel across lanes)
        if (lane < KT) {
            float c;
            if (lane == KT - 1) c = 1.0f;               // slot for q
            else {
                c = bp;
                for (int e = 0; e < KT - 2 - lane; e++) c *= ap;
            }
            scoef[lane] = c;
        }
    }
    // ---- Warps 4-7 (concurrent): p = Cw^T u, q = Cw^T b from smem ----
    if (tid >= 128) {
        const int d = tid - 128;
        float p = 0.f, q = 0.f;
        #pragma unroll 8
        for (int j = 0; j < H2c; j++) {
            const float cw = sCw[j * Dc + d];
            p += su[j] * cw;
            q += sBw[j] * cw;
        }
        sp[d] = p; sq[d] = q;
    }
    __syncthreads();                                   // sync2

    // ---- Dot from registers: k = 2r + wis (warp-uniform, 0..15) ----
    const float4 pv = reinterpret_cast<const float4*>(sp)[lane];
    const float4 qv = reinterpret_cast<const float4*>(sq)[lane];

    float acc = 0.f;
    #pragma unroll
    for (int r = 0; r < KT / 2; r++) {
        const int k = 2 * r + wis;                     // timestep, warp-uniform
        const float4 wv = (k == KT - 1) ? qv : pv;
        const float d = xv[r].x * wv.x + xv[r].y * wv.y
                      + xv[r].z * wv.z + xv[r].w * wv.w;
        acc += scoef[k] * d;
    }

    #pragma unroll
    for (int off = 16; off; off >>= 1) acc += __shfl_down_sync(FULL, acc, off);
    if (lane == 0) wsum[warp] = acc;
    __syncthreads();                                   // sync3
    if (tid < ROWS_PER_BLK)
        out[blockIdx.x * ROWS_PER_BLK + tid] = wsum[2 * tid] + wsum[2 * tid + 1];
}

extern "C" void kernel_launch(void* const* d_in, const int* in_sizes, int n_in,
                              void* d_out, int out_size)
{
    const float* inputs = (const float*)d_in[0];   // (1024, 512, 128)
    const float* C_w    = (const float*)d_in[1];   // (40, 128)
    const float* B_w    = (const float*)d_in[2];   // (1, 40)
    const float* refl   = (const float*)d_in[3];   // (2, 40)
    const float* theta  = (const float*)d_in[4];   // (3, 20)
    const float* mu0    = (const float*)d_in[5];   // (20,)
    float* out = (float*)d_out;                    // (1024,)

    urnn_fused<<<Nc / ROWS_PER_BLK, 256>>>(inputs, C_w, B_w, refl, theta, mu0, out);
}